// round 16
// baseline (speedup 1.0000x reference)
#include <cuda_runtime.h>

#define Bn 32
#define Tn 65536
#define TILE 2048
#define NT 32              /* tiles per row */
#define SEGCAP (Tn + 2)
#define BTH 256
#define SPT 8              /* samples per thread in scan kernels */
#define CHUNKN (BTH * SPT) /* 2048 = TILE: one scan block per tile */
#define NCHUNK 32
#define LAG 256
#define WIN (LAG + CHUNKN)
#define SWSZ (WIN + (WIN >> 5) + 4)
#define NTH_TOT (Bn * Tn / SPT)
#define SLOTS 64           /* max onsets per tile (P(>20) ~ 0) */

// ---------------- scratch (device globals) ----------------
static __device__ int    g_cnt[Bn * NT];              // per-tile onset counts
static __device__ float4 g_tP[Bn * NT];               // per-tile param totals
static __device__ int    g_tOn[Bn * NT];              // excl. onset offsets per tile
static __device__ int    g_Sl[Bn * NT * SLOTS];       // per-tile boundary positions
static __device__ float4 g_Bl[Bn * NT * SLOTS];       // per-tile boundary prefixes
static __device__ unsigned short g_segids[Bn * Tn];   // 4 MB (TILE-LOCAL ids)
static __device__ int    g_S[Bn * SEGCAP];
static __device__ float4 g_Bnd[Bn * SEGCAP];          // tile-local prefix at boundary
static __device__ float4 g_segA[Bn * SEGCAP];         // m00, m10, v1, v2
static __device__ float2 g_segB[Bn * SEGCAP];         // b0, mu
static __device__ float  g_segD[Bn * SEGCAP];         // dist
static __device__ float  g_xc[Bn * Tn];               // 8 MB (comb output)
static __device__ float4 g_pfxM[NTH_TOT];             // per-thread excl prefix (matrix)
static __device__ float2 g_pfxC[NTH_TOT];             // per-thread excl prefix (c)
static __device__ float4 g_chunkM[Bn * NCHUNK];
static __device__ float2 g_chunkC[Bn * NCHUNK];

#define MIN_W_F     0.007853981633974483f
#define LOG2_400_F  8.643856189774724f
#define LOG2_20_F   4.321928094887363f

__device__ __forceinline__ float fast_sigmoid(float v) {
    return __fdividef(1.0f, 1.0f + __expf(-v));
}
__device__ __forceinline__ int SW(int j) { return j + (j >> 5); }
__device__ __forceinline__ void pdl_wait() {
    asm volatile("griddepcontrol.wait;" ::: "memory");
}

// N = L after E  (2x2 affine compose)
#define COMPOSE(E00,E01,E10,E11,Ec1,Ec2, L00,L01,L10,L11,Lc1,Lc2, \
                N00,N01,N10,N11,Nc1,Nc2)                          \
    do {                                                          \
        N00 = fmaf(L00, E00, L01 * E10);                          \
        N01 = fmaf(L00, E01, L01 * E11);                          \
        N10 = fmaf(L10, E00, L11 * E10);                          \
        N11 = fmaf(L10, E01, L11 * E11);                          \
        Nc1 = fmaf(L00, Ec1, fmaf(L01, Ec2, Lc1));                \
        Nc2 = fmaf(L10, Ec1, fmaf(L11, Ec2, Lc2));                \
    } while (0)

// =====================================================================
// K1: TILE-LOCAL segids + boundary slots + per-tile totals (no deps!)
// =====================================================================
__global__ void __launch_bounds__(256) k_ids(const int4* __restrict__ onsets4,
                                             const float4* __restrict__ params) {
    int blk = blockIdx.x;
    long base = (long)blk * TILE;     // rows are contiguous: blk = row*NT + tile
    int tid = threadIdx.x, lane = tid & 31, wid = tid >> 5;

    __shared__ int    waggO[8];
    __shared__ float4 waggP[8];

    long ebase = base + (long)tid * 8;
    int4 oa = onsets4[ebase >> 2];
    int4 ob = onsets4[(ebase >> 2) + 1];
    int ol[8] = { oa.x, oa.y, oa.z, oa.w, ob.x, ob.y, ob.z, ob.w };
    float4 pl[8];
#pragma unroll
    for (int i = 0; i < 8; i++) pl[i] = params[ebase + i];

    int totO = 0;
    float4 totP = make_float4(0.f, 0.f, 0.f, 0.f);
#pragma unroll
    for (int i = 0; i < 8; i++) {
        totO += ol[i];
        totP.x += pl[i].x; totP.y += pl[i].y; totP.z += pl[i].z; totP.w += pl[i].w;
    }

    int inO = totO;
    float4 inP = totP;
#pragma unroll
    for (int off = 1; off < 32; off <<= 1) {
        int   eo = __shfl_up_sync(~0u, inO, off);
        float a = __shfl_up_sync(~0u, inP.x, off);
        float b = __shfl_up_sync(~0u, inP.y, off);
        float c = __shfl_up_sync(~0u, inP.z, off);
        float d = __shfl_up_sync(~0u, inP.w, off);
        if (lane >= off) { inO += eo; inP.x += a; inP.y += b; inP.z += c; inP.w += d; }
    }
    int exO = __shfl_up_sync(~0u, inO, 1);
    float4 exP;
    exP.x = __shfl_up_sync(~0u, inP.x, 1);
    exP.y = __shfl_up_sync(~0u, inP.y, 1);
    exP.z = __shfl_up_sync(~0u, inP.z, 1);
    exP.w = __shfl_up_sync(~0u, inP.w, 1);
    if (lane == 0) { exO = 0; exP = make_float4(0.f, 0.f, 0.f, 0.f); }
    if (lane == 31) { waggO[wid] = inO; waggP[wid] = inP; }
    __syncthreads();

    int weO = 0;
    float4 weP = make_float4(0.f, 0.f, 0.f, 0.f);
#pragma unroll
    for (int w = 0; w < 8; w++) {
        if (w < wid) {
            weO += waggO[w];
            weP.x += waggP[w].x; weP.y += waggP[w].y;
            weP.z += waggP[w].z; weP.w += waggP[w].w;
        }
    }

    int id = weO + exO;                         // tile-local id
    float4 pex = make_float4(weP.x + exP.x, weP.y + exP.y,
                             weP.z + exP.z, weP.w + exP.w);
    int slot0 = blk * SLOTS;
    unsigned w01 = 0, w23 = 0, w45 = 0, w67 = 0;
#pragma unroll
    for (int i = 0; i < 8; i++) {
        id += ol[i];
        unsigned u = (unsigned)id & 0xffffu;
        if (i == 0) w01 = u;        else if (i == 1) w01 |= u << 16;
        else if (i == 2) w23 = u;   else if (i == 3) w23 |= u << 16;
        else if (i == 4) w45 = u;   else if (i == 5) w45 |= u << 16;
        else if (i == 6) w67 = u;   else              w67 |= u << 16;
        if (ol[i]) {
            g_Sl[slot0 + id - 1] = (int)(ebase + i) & (Tn - 1);  // position in row
            g_Bl[slot0 + id - 1] = pex;
        }
        pex.x += pl[i].x; pex.y += pl[i].y; pex.z += pl[i].z; pex.w += pl[i].w;
    }
    *(uint4*)&g_segids[ebase] = make_uint4(w01, w23, w45, w67);

    if (tid == 255) {
        g_cnt[blk] = id;
        g_tP[blk] = pex;
    }
}

// =====================================================================
// K2: per-row — scan tile counts/totals, compact boundaries into
//     global S/Bnd, write sentinels + g_tOn, build segment tables.
// =====================================================================
__global__ void __launch_bounds__(256) k_segc() {
    __shared__ float4 tOff[NT];
    __shared__ int    tOn[NT];
    __shared__ int    s_nOn;

    pdl_wait();
    int srow = blockIdx.x;
    int ro0 = srow * SEGCAP;
    int tid = threadIdx.x, lane = tid & 31;

    if (tid < 32) {
        int rb = (srow << 5) + lane;
        int c = g_cnt[rb];
        float4 p = g_tP[rb];
        int ic = c;
        float4 ip = p;
#pragma unroll
        for (int off = 1; off < 32; off <<= 1) {
            int   ec = __shfl_up_sync(~0u, ic, off);
            float a = __shfl_up_sync(~0u, ip.x, off);
            float b = __shfl_up_sync(~0u, ip.y, off);
            float cc = __shfl_up_sync(~0u, ip.z, off);
            float d = __shfl_up_sync(~0u, ip.w, off);
            if (lane >= off) { ic += ec; ip.x += a; ip.y += b; ip.z += cc; ip.w += d; }
        }
        int ex = ic - c;
        tOn[lane] = ex;
        tOff[lane] = make_float4(ip.x - p.x, ip.y - p.y, ip.z - p.z, ip.w - p.w);
        g_tOn[rb] = ex;
        if (lane == 31) {
            s_nOn = ic;
            g_S[ro0] = 0;
            g_Bnd[ro0] = make_float4(0.f, 0.f, 0.f, 0.f);
            g_S[ro0 + ic + 1] = Tn;
            g_Bnd[ro0 + ic + 1] = p;        // tile 31 local total
        }
    }
    __syncthreads();
    int nOn = s_nOn;

    // compact per-tile boundary slots into global arrays
    for (int s = tid; s < NT * SLOTS; s += 256) {
        int t = s >> 6, j = s & (SLOTS - 1);
        if (j < g_cnt[(srow << 5) + t]) {
            int g = tOn[t] + j + 1;
            int src = ((srow << 5) + t) * SLOTS + j;
            g_S[ro0 + g] = g_Sl[src];
            g_Bnd[ro0 + g] = g_Bl[src];
        }
    }
    __syncthreads();

    // build tables
    for (int s = tid; s <= nOn; s += 256) {
        int r2 = ro0 + s;
        int S0 = g_S[r2], S1 = g_S[r2 + 1];
        int t0 = S0 >> 11;
        int t1 = min(S1 >> 11, NT - 1);
        float4 O0 = tOff[t0], O1 = tOff[t1];
        float4 B0 = g_Bnd[r2], B1 = g_Bnd[r2 + 1];
        float sx = (O1.x + B1.x) - (O0.x + B0.x);
        float sy = (O1.y + B1.y) - (O0.y + B0.y);
        float sz = (O1.z + B1.z) - (O0.z + B0.z);
        float sw4 = (O1.w + B1.w) - (O0.w + B0.w);

        float invc = __fdividef(1.f, fmaxf((float)(S1 - S0), 1.f));
        float dist = 0.1f * exp2f(fast_sigmoid(sx * invc) * LOG2_20_F);
        float wmod = fast_sigmoid(sy * invc);
        float qmod = fast_sigmoid(sz * invc);
        float mu   = fast_sigmoid(sw4 * invc);

        float w = MIN_W_F * exp2f(wmod * LOG2_400_F);
        float q = 0.1f * exp2f(qmod * LOG2_20_F);
        float sh, ch;
        __sincosf(0.5f * w, &sh, &ch);
        float omc = 2.f * sh * sh;
        float cw = 1.f - omc;
        float sw = 2.f * sh * ch;
        float alpha = __fdividef(sw, 2.f * q);
        float inva0 = __fdividef(1.f, 1.f + alpha);
        float b0 = 0.5f * omc * inva0;
        float b1c = omc * inva0;
        float a1 = -2.f * cw * inva0;
        float a2 = (1.f - alpha) * inva0;

        g_segA[r2] = make_float4(-a1, -a2, b1c - a1 * b0, b0 - a2 * b0);
        g_segB[r2] = make_float2(b0, mu);
        g_segD[r2] = dist;
    }
}

// =====================================================================
// helpers
// =====================================================================
__device__ __forceinline__ void unpack_ids(uint4 sv, int ids[SPT]) {
    ids[0] = sv.x & 0xffff; ids[1] = sv.x >> 16;
    ids[2] = sv.y & 0xffff; ids[3] = sv.y >> 16;
    ids[4] = sv.z & 0xffff; ids[5] = sv.z >> 16;
    ids[6] = sv.w & 0xffff; ids[7] = sv.w >> 16;
}

__device__ __forceinline__ void compose_thread(const int ids[SPT], bool uni,
        int tabOff, float4 T0, const float xc[SPT],
        float& A00, float& A01, float& A10, float& A11, float& c1, float& c2) {
    float4 T = T0;
    A00 = 1.f; A01 = 0.f; A10 = 0.f; A11 = 1.f; c1 = 0.f; c2 = 0.f;
#pragma unroll
    for (int i = 0; i < SPT; i++) {
        if (!uni && i) T = g_segA[tabOff + ids[i]];
        float n00 = fmaf(T.x, A00, A10);
        float n01 = fmaf(T.x, A01, A11);
        float n10 = T.y * A00;
        float n11 = T.y * A01;
        float t1  = fmaf(T.z, xc[i], fmaf(T.x, c1, c2));
        float t2  = fmaf(T.w, xc[i], T.y * c1);
        A00 = n00; A01 = n01; A10 = n10; A11 = n11; c1 = t1; c2 = t2;
    }
}

// =====================================================================
// K3: stage x*dist + comb + block scan; stores xc, per-thread prefix,
//     chunk aggregate. One block == one tile: uniform table offset.
// =====================================================================
__global__ void __launch_bounds__(BTH) k_scanA(const float* __restrict__ x,
                                               const float* __restrict__ f0) {
    __shared__ float sxd[SWSZ];
    __shared__ float wagg[8][6];
    __shared__ float sWex[8][6];

    int tid = threadIdx.x, blk = blockIdx.x;
    int lane = tid & 31, wid = tid >> 5;
    int base = blk * CHUNKN;
    int row = base >> 16;
    int tile = blk & (NT - 1);
    int rowoff = row * SEGCAP;
    int lbase = tid * SPT;
    int gbase = base + lbase;

    // independent prologue (overlaps k_segc tail via PDL)
    float4 f0a = *(const float4*)&f0[gbase];
    float4 f0b = *(const float4*)&f0[gbase + 4];
    float f0v[SPT] = { f0a.x, f0a.y, f0a.z, f0a.w, f0b.x, f0b.y, f0b.z, f0b.w };

    pdl_wait();

    int tabOff = rowoff + g_tOn[(row << 5) + tile];
    int tabPrev = (tile > 0) ? rowoff + g_tOn[(row << 5) + tile - 1] : 0;

    // stage xd = x*dist over [base-LAG, base+CHUNKN)
#pragma unroll
    for (int k = tid; k < WIN / 4; k += BTH) {
        int off = k << 2;
        float4 v = make_float4(0.f, 0.f, 0.f, 0.f);
        if (tile > 0 || off >= LAG) {
            int g = base - LAG + off;
            int tb = (off < LAG) ? tabPrev : tabOff;
            float4 xv = *(const float4*)&x[g];
            uint2 sv = *(const uint2*)&g_segids[g];
            int i0 = (int)(sv.x & 0xffff), i3 = (int)(sv.y >> 16);
            if (i0 == i3) {
                float d = g_segD[tb + i0];
                v = make_float4(xv.x * d, xv.y * d, xv.z * d, xv.w * d);
            } else {
                v.x = xv.x * g_segD[tb + i0];
                v.y = xv.y * g_segD[tb + (int)(sv.x >> 16)];
                v.z = xv.z * g_segD[tb + (int)(sv.y & 0xffff)];
                v.w = xv.w * g_segD[tb + i3];
            }
        }
        sxd[SW(off)]     = v.x;
        sxd[SW(off + 1)] = v.y;
        sxd[SW(off + 2)] = v.z;
        sxd[SW(off + 3)] = v.w;
    }
    __syncthreads();

    int ids[SPT];
    unpack_ids(*(const uint4*)&g_segids[gbase], ids);
    bool uni = (ids[0] == ids[SPT - 1]);
    float4 T = g_segA[tabOff + ids[0]];
    float2 Bc = g_segB[tabOff + ids[0]];

    float xc[SPT];
#pragma unroll
    for (int i = 0; i < SPT; i++) {
        if (!uni && i) Bc = g_segB[tabOff + ids[i]];
        float p = f0v[i] * Bc.y;
        int zi = (int)p;
        float alfa = p - (float)zi;
        int li = lbase + i + LAG;
        float x1 = sxd[SW(li - zi - 1)];
        float x2 = sxd[SW(li - zi - 2)];
        xc[i] = fmaf(alfa, x1 - x2, sxd[SW(li)] - x1);
    }
    *(float4*)&g_xc[gbase]     = make_float4(xc[0], xc[1], xc[2], xc[3]);
    *(float4*)&g_xc[gbase + 4] = make_float4(xc[4], xc[5], xc[6], xc[7]);

    float I00, I01, I10, I11, Ic1, Ic2;
    compose_thread(ids, uni, tabOff, T, xc, I00, I01, I10, I11, Ic1, Ic2);

    // warp inclusive KS
#pragma unroll
    for (int off = 1; off < 32; off <<= 1) {
        float E00 = __shfl_up_sync(~0u, I00, off);
        float E01 = __shfl_up_sync(~0u, I01, off);
        float E10 = __shfl_up_sync(~0u, I10, off);
        float E11 = __shfl_up_sync(~0u, I11, off);
        float Ec1 = __shfl_up_sync(~0u, Ic1, off);
        float Ec2 = __shfl_up_sync(~0u, Ic2, off);
        if (lane >= off) {
            float N00, N01, N10, N11, Nc1, Nc2;
            COMPOSE(E00,E01,E10,E11,Ec1,Ec2, I00,I01,I10,I11,Ic1,Ic2,
                    N00,N01,N10,N11,Nc1,Nc2);
            I00 = N00; I01 = N01; I10 = N10; I11 = N11; Ic1 = Nc1; Ic2 = Nc2;
        }
    }
    float X00 = __shfl_up_sync(~0u, I00, 1);
    float X01 = __shfl_up_sync(~0u, I01, 1);
    float X10 = __shfl_up_sync(~0u, I10, 1);
    float X11 = __shfl_up_sync(~0u, I11, 1);
    float Xc1 = __shfl_up_sync(~0u, Ic1, 1);
    float Xc2 = __shfl_up_sync(~0u, Ic2, 1);
    if (lane == 0) { X00 = 1.f; X01 = 0.f; X10 = 0.f; X11 = 1.f; Xc1 = 0.f; Xc2 = 0.f; }
    if (lane == 31) {
        wagg[wid][0] = I00; wagg[wid][1] = I01; wagg[wid][2] = I10;
        wagg[wid][3] = I11; wagg[wid][4] = Ic1; wagg[wid][5] = Ic2;
    }
    __syncthreads();

    if (wid == 0 && lane < 8) {
        float W00 = wagg[lane][0], W01 = wagg[lane][1], W10 = wagg[lane][2];
        float W11 = wagg[lane][3], Wc1 = wagg[lane][4], Wc2 = wagg[lane][5];
#pragma unroll
        for (int off = 1; off < 8; off <<= 1) {
            float E00 = __shfl_up_sync(0xffu, W00, off);
            float E01 = __shfl_up_sync(0xffu, W01, off);
            float E10 = __shfl_up_sync(0xffu, W10, off);
            float E11 = __shfl_up_sync(0xffu, W11, off);
            float Ec1 = __shfl_up_sync(0xffu, Wc1, off);
            float Ec2 = __shfl_up_sync(0xffu, Wc2, off);
            if (lane >= off) {
                float N00, N01, N10, N11, Nc1, Nc2;
                COMPOSE(E00,E01,E10,E11,Ec1,Ec2, W00,W01,W10,W11,Wc1,Wc2,
                        N00,N01,N10,N11,Nc1,Nc2);
                W00 = N00; W01 = N01; W10 = N10; W11 = N11; Wc1 = Nc1; Wc2 = Nc2;
            }
        }
        float P00 = __shfl_up_sync(0xffu, W00, 1);
        float P01 = __shfl_up_sync(0xffu, W01, 1);
        float P10 = __shfl_up_sync(0xffu, W10, 1);
        float P11 = __shfl_up_sync(0xffu, W11, 1);
        float Pc1 = __shfl_up_sync(0xffu, Wc1, 1);
        float Pc2 = __shfl_up_sync(0xffu, Wc2, 1);
        if (lane == 0) { P00 = 1.f; P01 = 0.f; P10 = 0.f; P11 = 1.f; Pc1 = 0.f; Pc2 = 0.f; }
        sWex[lane][0] = P00; sWex[lane][1] = P01; sWex[lane][2] = P10;
        sWex[lane][3] = P11; sWex[lane][4] = Pc1; sWex[lane][5] = Pc2;
        if (lane == 7) {
            g_chunkM[blk] = make_float4(W00, W01, W10, W11);
            g_chunkC[blk] = make_float2(Wc1, Wc2);
        }
    }
    __syncthreads();

    float E00 = sWex[wid][0], E01 = sWex[wid][1], E10 = sWex[wid][2];
    float E11 = sWex[wid][3], Ec1 = sWex[wid][4], Ec2 = sWex[wid][5];
    float P00, P01, P10, P11, Pc1, Pc2;
    COMPOSE(E00,E01,E10,E11,Ec1,Ec2, X00,X01,X10,X11,Xc1,Xc2,
            P00,P01,P10,P11,Pc1,Pc2);
    int gidx = blk * BTH + tid;
    g_pfxM[gidx] = make_float4(P00, P01, P10, P11);
    g_pfxC[gidx] = make_float2(Pc1, Pc2);
}

// =====================================================================
// K4: replay — elementwise from xc + prefix; warp0 cin scan
// =====================================================================
__global__ void __launch_bounds__(BTH) k_replay(float* __restrict__ out) {
    __shared__ float2 s_cin;

    int tid = threadIdx.x, lane = tid & 31, wid = tid >> 5;
    int blk = blockIdx.x;
    int base = blk * CHUNKN;
    int row = base >> 16;
    int tile = blk & (NT - 1);
    int rowoff = row * SEGCAP;
    int gbase = base + tid * SPT;
    int gidx = blk * BTH + tid;

    pdl_wait();

    int tabOff = rowoff + g_tOn[(row << 5) + tile];
    float4 PM = g_pfxM[gidx];
    float2 PC = g_pfxC[gidx];
    int ids[SPT];
    unpack_ids(*(const uint4*)&g_segids[gbase], ids);
    bool uni = (ids[0] == ids[SPT - 1]);
    float4 xa = *(const float4*)&g_xc[gbase];
    float4 xb = *(const float4*)&g_xc[gbase + 4];
    float xc[SPT] = { xa.x, xa.y, xa.z, xa.w, xb.x, xb.y, xb.z, xb.w };

    if (wid == 0) {
        int chunk = blk & (NCHUNK - 1);
        int rowBlk = blk - chunk;
        float T00 = 1.f, T01 = 0.f, T10 = 0.f, T11 = 1.f, Tc1 = 0.f, Tc2 = 0.f;
        if (lane < chunk) {
            float4 M = g_chunkM[rowBlk + lane];
            float2 C = g_chunkC[rowBlk + lane];
            T00 = M.x; T01 = M.y; T10 = M.z; T11 = M.w; Tc1 = C.x; Tc2 = C.y;
        }
#pragma unroll
        for (int off = 1; off < 32; off <<= 1) {
            float E00 = __shfl_up_sync(~0u, T00, off);
            float E01 = __shfl_up_sync(~0u, T01, off);
            float E10 = __shfl_up_sync(~0u, T10, off);
            float E11 = __shfl_up_sync(~0u, T11, off);
            float Ec1 = __shfl_up_sync(~0u, Tc1, off);
            float Ec2 = __shfl_up_sync(~0u, Tc2, off);
            if (lane >= off) {
                float N00, N01, N10, N11, Nc1, Nc2;
                COMPOSE(E00,E01,E10,E11,Ec1,Ec2, T00,T01,T10,T11,Tc1,Tc2,
                        N00,N01,N10,N11,Nc1,Nc2);
                T00 = N00; T01 = N01; T10 = N10; T11 = N11; Tc1 = Nc1; Tc2 = Nc2;
            }
        }
        float i1 = 0.f, i2 = 0.f;
        if (chunk > 0) {
            i1 = __shfl_sync(~0u, Tc1, chunk - 1);
            i2 = __shfl_sync(~0u, Tc2, chunk - 1);
        }
        if (lane == 0) s_cin = make_float2(i1, i2);
    }
    __syncthreads();

    float2 cin = s_cin;
    float st1 = fmaf(PM.x, cin.x, fmaf(PM.y, cin.y, PC.x));
    float st2 = fmaf(PM.z, cin.x, fmaf(PM.w, cin.y, PC.y));

    float4 T = g_segA[tabOff + ids[0]];
    float2 Bc = g_segB[tabOff + ids[0]];
    float ov[SPT];
#pragma unroll
    for (int i = 0; i < SPT; i++) {
        if (!uni && i) { T = g_segA[tabOff + ids[i]]; Bc = g_segB[tabOff + ids[i]]; }
        ov[i] = fmaf(Bc.x, xc[i], st1);
        float n1 = fmaf(T.z, xc[i], fmaf(T.x, st1, st2));
        float n2 = fmaf(T.w, xc[i], T.y * st1);
        st1 = n1; st2 = n2;
    }
    *(float4*)&out[gbase]     = make_float4(ov[0], ov[1], ov[2], ov[3]);
    *(float4*)&out[gbase + 4] = make_float4(ov[4], ov[5], ov[6], ov[7]);
}

// =====================================================================
template <typename F, typename... Args>
static void launch_pdl(F fn, int grid, int block, Args... args) {
    cudaLaunchConfig_t cfg = {};
    cfg.gridDim = dim3(grid, 1, 1);
    cfg.blockDim = dim3(block, 1, 1);
    cudaLaunchAttribute attr[1];
    attr[0].id = cudaLaunchAttributeProgrammaticStreamSerialization;
    attr[0].val.programmaticStreamSerializationAllowed = 1;
    cfg.attrs = attr;
    cfg.numAttrs = 1;
    cudaLaunchKernelEx(&cfg, fn, args...);
}

extern "C" void kernel_launch(void* const* d_in, const int* in_sizes, int n_in,
                              void* d_out, int out_size) {
    const float* f0     = (const float*)d_in[0];
    const float* x      = (const float*)d_in[1];
    const float* params = (const float*)d_in[2];
    const int*   onsets = (const int*)d_in[3];
    float* out = (float*)d_out;

    k_ids<<<Bn * NT, 256>>>((const int4*)onsets, (const float4*)params);
    launch_pdl(k_segc,   Bn,          256);
    launch_pdl(k_scanA,  Bn * NCHUNK, BTH, x, f0);
    launch_pdl(k_replay, Bn * NCHUNK, BTH, out);
}

// round 17
// speedup vs baseline: 1.0599x; 1.0599x over previous
#include <cuda_runtime.h>

#define Bn 32
#define Tn 65536
#define TILE 2048
#define NT 32              /* tiles per row */
#define SEGCAP (Tn + 2)
#define NCHUNK 32
#define BTH 256
#define SPT 8              /* samples per thread in scan kernels */
#define LAG 256            /* staged history for comb (max lag ~202) */
#define CHUNKN (BTH * SPT) /* 2048 samples per scan block */
#define WIN (LAG + CHUNKN)
#define SWSZ (WIN + (WIN >> 5) + 4)
#define NTH_TOT (Bn * Tn / SPT)   /* 262144 scan threads */
#define NBLK (Bn * NCHUNK)        /* 1024 scan blocks */

// ---------------- scratch (device globals) ----------------
static __device__ int    g_tO[Bn * NT];
static __device__ float4 g_tP[Bn * NT];
static __device__ int    g_nOn[Bn];
static __device__ unsigned short g_segids[Bn * Tn];  // 4 MB
static __device__ int    g_S[Bn * SEGCAP];
static __device__ float4 g_Bnd[Bn * SEGCAP];         // tile-local prefix at boundary
static __device__ float4 g_segA[Bn * SEGCAP];        // m00, m10, v1, v2
static __device__ float2 g_segB[Bn * SEGCAP];        // b0, mu
static __device__ float  g_segD[Bn * SEGCAP];        // dist
static __device__ float  g_xc[Bn * Tn];              // 8 MB (comb output)
static __device__ float4 g_pfxM[NTH_TOT];            // 4 MB per-thread excl prefix (matrix)
static __device__ float2 g_pfxC[NTH_TOT];            // 2 MB per-thread excl prefix (c)
static __device__ float4 g_chunkM[NBLK];
static __device__ float2 g_chunkC[NBLK];
static __device__ float2 g_cin[NBLK];                // incoming state per chunk

#define MIN_W_F     0.007853981633974483f
#define LOG2_400_F  8.643856189774724f
#define LOG2_20_F   4.321928094887363f

__device__ __forceinline__ float fast_sigmoid(float v) {
    return __fdividef(1.0f, 1.0f + __expf(-v));
}
__device__ __forceinline__ int SW(int j) { return j + (j >> 5); }
__device__ __forceinline__ void pdl_wait() {
    asm volatile("griddepcontrol.wait;" ::: "memory");
}

// N = L after E  (2x2 affine compose)
#define COMPOSE(E00,E01,E10,E11,Ec1,Ec2, L00,L01,L10,L11,Lc1,Lc2, \
                N00,N01,N10,N11,Nc1,Nc2)                          \
    do {                                                          \
        N00 = fmaf(L00, E00, L01 * E10);                          \
        N01 = fmaf(L00, E01, L01 * E11);                          \
        N10 = fmaf(L10, E00, L11 * E10);                          \
        N11 = fmaf(L10, E01, L11 * E11);                          \
        Nc1 = fmaf(L00, Ec1, fmaf(L01, Ec2, Lc1));                \
        Nc2 = fmaf(L10, Ec1, fmaf(L11, Ec2, Lc2));                \
    } while (0)

// =====================================================================
// K1: per-tile ONSET totals only
// =====================================================================
__global__ void __launch_bounds__(256) k_tile(const int4* __restrict__ onsets4) {
    int blk = blockIdx.x;
    long base4 = (long)blk * (TILE / 4);
    int tid = threadIdx.x;

    int o = 0;
#pragma unroll
    for (int k = 0; k < 2; k++) {
        int4 v = onsets4[base4 + k * 256 + tid];
        o += v.x + v.y + v.z + v.w;
    }
#pragma unroll
    for (int off = 16; off; off >>= 1)
        o += __shfl_down_sync(~0u, o, off);
    __shared__ int so[8];
    int lane = tid & 31, wid = tid >> 5;
    if (lane == 0) so[wid] = o;
    __syncthreads();
    if (tid == 0) {
        int ot = 0;
#pragma unroll
        for (int w = 0; w < 8; w++) ot += so[w];
        g_tO[blk] = ot;
    }
}

// =====================================================================
// K2: segids (packed u16x8) + tile-local boundary prefixes + tile totals
// =====================================================================
__global__ void __launch_bounds__(256) k_ids(const int4* __restrict__ onsets4,
                                             const float4* __restrict__ params) {
    int blk = blockIdx.x;
    int row = blk >> 5, tile = blk & (NT - 1);
    long rowbase = (long)row * Tn;
    long base = rowbase + (long)tile * TILE;
    int tid = threadIdx.x, lane = tid & 31, wid = tid >> 5;
    int rowoff = row * SEGCAP;

    __shared__ int    waggO[8];
    __shared__ float4 waggP[8];
    __shared__ int    s_carO;

    long ebase = base + (long)tid * 8;
    int4 oa = onsets4[ebase >> 2];
    int4 ob = onsets4[(ebase >> 2) + 1];
    int ol[8] = { oa.x, oa.y, oa.z, oa.w, ob.x, ob.y, ob.z, ob.w };
    float4 pl[8];
#pragma unroll
    for (int i = 0; i < 8; i++) pl[i] = params[ebase + i];

    pdl_wait();

    if (wid == 0) {
        int co = 0;
        if (lane < tile) co = g_tO[(row << 5) + lane];
#pragma unroll
        for (int off = 16; off; off >>= 1)
            co += __shfl_down_sync(~0u, co, off);
        if (lane == 0) s_carO = co;
    }

    int totO = 0;
    float4 totP = make_float4(0.f, 0.f, 0.f, 0.f);
#pragma unroll
    for (int i = 0; i < 8; i++) {
        totO += ol[i];
        totP.x += pl[i].x; totP.y += pl[i].y; totP.z += pl[i].z; totP.w += pl[i].w;
    }

    int inO = totO;
    float4 inP = totP;
#pragma unroll
    for (int off = 1; off < 32; off <<= 1) {
        int   eo = __shfl_up_sync(~0u, inO, off);
        float a = __shfl_up_sync(~0u, inP.x, off);
        float b = __shfl_up_sync(~0u, inP.y, off);
        float c = __shfl_up_sync(~0u, inP.z, off);
        float d = __shfl_up_sync(~0u, inP.w, off);
        if (lane >= off) { inO += eo; inP.x += a; inP.y += b; inP.z += c; inP.w += d; }
    }
    int exO = __shfl_up_sync(~0u, inO, 1);
    float4 exP;
    exP.x = __shfl_up_sync(~0u, inP.x, 1);
    exP.y = __shfl_up_sync(~0u, inP.y, 1);
    exP.z = __shfl_up_sync(~0u, inP.z, 1);
    exP.w = __shfl_up_sync(~0u, inP.w, 1);
    if (lane == 0) { exO = 0; exP = make_float4(0.f, 0.f, 0.f, 0.f); }
    if (lane == 31) { waggO[wid] = inO; waggP[wid] = inP; }
    __syncthreads();

    int weO = 0;
    float4 weP = make_float4(0.f, 0.f, 0.f, 0.f);
#pragma unroll
    for (int w = 0; w < 8; w++) {
        if (w < wid) {
            weO += waggO[w];
            weP.x += waggP[w].x; weP.y += waggP[w].y;
            weP.z += waggP[w].z; weP.w += waggP[w].w;
        }
    }

    int carO = s_carO;
    if (tid == 0 && tile == 0) {
        g_S[rowoff] = 0;
        g_Bnd[rowoff] = make_float4(0.f, 0.f, 0.f, 0.f);
    }

    int id = carO + weO + exO;
    float4 pex = make_float4(weP.x + exP.x, weP.y + exP.y,
                             weP.z + exP.z, weP.w + exP.w);
    unsigned w01 = 0, w23 = 0, w45 = 0, w67 = 0;
#pragma unroll
    for (int i = 0; i < 8; i++) {
        id += ol[i];
        unsigned u = (unsigned)id & 0xffffu;
        if (i == 0) w01 = u;        else if (i == 1) w01 |= u << 16;
        else if (i == 2) w23 = u;   else if (i == 3) w23 |= u << 16;
        else if (i == 4) w45 = u;   else if (i == 5) w45 |= u << 16;
        else if (i == 6) w67 = u;   else              w67 |= u << 16;
        if (ol[i]) {
            g_S[rowoff + id] = (int)(ebase + i - rowbase);
            g_Bnd[rowoff + id] = pex;
        }
        pex.x += pl[i].x; pex.y += pl[i].y; pex.z += pl[i].z; pex.w += pl[i].w;
    }
    *(uint4*)&g_segids[ebase] = make_uint4(w01, w23, w45, w67);

    if (tid == 255) {
        g_tP[blk] = pex;
        if (tile == NT - 1) {
            g_nOn[row] = id;
            g_S[rowoff + id + 1]   = Tn;
            g_Bnd[rowoff + id + 1] = pex;
        }
    }
}

// =====================================================================
// K3: per-segment coefficient tables (tile offsets -> global prefixes)
// =====================================================================
__global__ void __launch_bounds__(256) k_segc() {
    __shared__ float4 tOff[NT];

    pdl_wait();
    int srow = blockIdx.x;
    int ro0 = srow * SEGCAP;
    int tid = threadIdx.x, lane = tid & 31;

    if (tid < 32) {
        float4 p = g_tP[(srow << 5) + lane];
        float4 ip = p;
#pragma unroll
        for (int off = 1; off < 32; off <<= 1) {
            float a = __shfl_up_sync(~0u, ip.x, off);
            float b = __shfl_up_sync(~0u, ip.y, off);
            float c = __shfl_up_sync(~0u, ip.z, off);
            float d = __shfl_up_sync(~0u, ip.w, off);
            if (lane >= off) { ip.x += a; ip.y += b; ip.z += c; ip.w += d; }
        }
        tOff[lane] = make_float4(ip.x - p.x, ip.y - p.y, ip.z - p.z, ip.w - p.w);
    }
    __syncthreads();

    int nOn = g_nOn[srow];
    for (int s = tid; s <= nOn; s += 256) {
        int r2 = ro0 + s;
        int S0 = g_S[r2], S1 = g_S[r2 + 1];
        int t0 = S0 >> 11;
        int t1 = min(S1 >> 11, NT - 1);
        float4 O0 = tOff[t0], O1 = tOff[t1];
        float4 B0 = g_Bnd[r2], B1 = g_Bnd[r2 + 1];
        float sx = (O1.x + B1.x) - (O0.x + B0.x);
        float sy = (O1.y + B1.y) - (O0.y + B0.y);
        float sz = (O1.z + B1.z) - (O0.z + B0.z);
        float sw4 = (O1.w + B1.w) - (O0.w + B0.w);

        float invc = __fdividef(1.f, fmaxf((float)(S1 - S0), 1.f));
        float dist = 0.1f * exp2f(fast_sigmoid(sx * invc) * LOG2_20_F);
        float wmod = fast_sigmoid(sy * invc);
        float qmod = fast_sigmoid(sz * invc);
        float mu   = fast_sigmoid(sw4 * invc);

        float w = MIN_W_F * exp2f(wmod * LOG2_400_F);
        float q = 0.1f * exp2f(qmod * LOG2_20_F);
        float sh, ch;
        __sincosf(0.5f * w, &sh, &ch);
        float omc = 2.f * sh * sh;
        float cw = 1.f - omc;
        float sw = 2.f * sh * ch;
        float alpha = __fdividef(sw, 2.f * q);
        float inva0 = __fdividef(1.f, 1.f + alpha);
        float b0 = 0.5f * omc * inva0;
        float b1c = omc * inva0;
        float a1 = -2.f * cw * inva0;
        float a2 = (1.f - alpha) * inva0;

        g_segA[r2] = make_float4(-a1, -a2, b1c - a1 * b0, b0 - a2 * b0);
        g_segB[r2] = make_float2(b0, mu);
        g_segD[r2] = dist;
    }
}

// =====================================================================
// helpers
// =====================================================================
__device__ __forceinline__ void unpack_ids(uint4 sv, int ids[SPT]) {
    ids[0] = sv.x & 0xffff; ids[1] = sv.x >> 16;
    ids[2] = sv.y & 0xffff; ids[3] = sv.y >> 16;
    ids[4] = sv.z & 0xffff; ids[5] = sv.z >> 16;
    ids[6] = sv.w & 0xffff; ids[7] = sv.w >> 16;
}

__device__ __forceinline__ void compose_thread(const int ids[SPT], bool uni,
        int rowoff, float4 T0, const float xc[SPT],
        float& A00, float& A01, float& A10, float& A11, float& c1, float& c2) {
    float4 T = T0;
    A00 = 1.f; A01 = 0.f; A10 = 0.f; A11 = 1.f; c1 = 0.f; c2 = 0.f;
#pragma unroll
    for (int i = 0; i < SPT; i++) {
        if (!uni && i) T = g_segA[rowoff + ids[i]];
        float n00 = fmaf(T.x, A00, A10);
        float n01 = fmaf(T.x, A01, A11);
        float n10 = T.y * A00;
        float n11 = T.y * A01;
        float t1  = fmaf(T.z, xc[i], fmaf(T.x, c1, c2));
        float t2  = fmaf(T.w, xc[i], T.y * c1);
        A00 = n00; A01 = n01; A10 = n10; A11 = n11; c1 = t1; c2 = t2;
    }
}

// =====================================================================
// K4: stage x*dist + comb + block scan; stores xc, per-thread prefix,
//     chunk aggregate.
// =====================================================================
__global__ void __launch_bounds__(BTH) k_scanA(const float* __restrict__ x,
                                               const float* __restrict__ f0) {
    __shared__ float sxd[SWSZ];
    __shared__ float wagg[8][6];
    __shared__ float sWex[8][6];

    int tid = threadIdx.x, blk = blockIdx.x;
    int lane = tid & 31, wid = tid >> 5;
    int base = blk * CHUNKN;
    int t0 = base & (Tn - 1);
    int rowoff = (base >> 16) * SEGCAP;
    int lbase = tid * SPT;
    int gbase = base + lbase;

    float4 f0a = *(const float4*)&f0[gbase];
    float4 f0b = *(const float4*)&f0[gbase + 4];
    float f0v[SPT] = { f0a.x, f0a.y, f0a.z, f0a.w, f0b.x, f0b.y, f0b.z, f0b.w };

    pdl_wait();

#pragma unroll
    for (int k = tid; k < WIN / 4; k += BTH) {
        int off = k << 2;
        float4 v = make_float4(0.f, 0.f, 0.f, 0.f);
        if (t0 + off >= LAG) {
            int g = base - LAG + off;
            float4 xv = *(const float4*)&x[g];
            uint2 sv = *(const uint2*)&g_segids[g];
            int i0 = (int)(sv.x & 0xffff), i3 = (int)(sv.y >> 16);
            if (i0 == i3) {
                float d = g_segD[rowoff + i0];
                v = make_float4(xv.x * d, xv.y * d, xv.z * d, xv.w * d);
            } else {
                v.x = xv.x * g_segD[rowoff + i0];
                v.y = xv.y * g_segD[rowoff + (int)(sv.x >> 16)];
                v.z = xv.z * g_segD[rowoff + (int)(sv.y & 0xffff)];
                v.w = xv.w * g_segD[rowoff + i3];
            }
        }
        sxd[SW(off)]     = v.x;
        sxd[SW(off + 1)] = v.y;
        sxd[SW(off + 2)] = v.z;
        sxd[SW(off + 3)] = v.w;
    }
    __syncthreads();

    int ids[SPT];
    unpack_ids(*(const uint4*)&g_segids[gbase], ids);
    bool uni = (ids[0] == ids[SPT - 1]);
    float4 T = g_segA[rowoff + ids[0]];
    float2 Bc = g_segB[rowoff + ids[0]];

    float xc[SPT];
#pragma unroll
    for (int i = 0; i < SPT; i++) {
        if (!uni && i) Bc = g_segB[rowoff + ids[i]];
        float p = f0v[i] * Bc.y;
        int zi = (int)p;
        float alfa = p - (float)zi;
        int li = lbase + i + LAG;
        float x1 = sxd[SW(li - zi - 1)];
        float x2 = sxd[SW(li - zi - 2)];
        xc[i] = fmaf(alfa, x1 - x2, sxd[SW(li)] - x1);
    }
    *(float4*)&g_xc[gbase]     = make_float4(xc[0], xc[1], xc[2], xc[3]);
    *(float4*)&g_xc[gbase + 4] = make_float4(xc[4], xc[5], xc[6], xc[7]);

    float I00, I01, I10, I11, Ic1, Ic2;
    compose_thread(ids, uni, rowoff, T, xc, I00, I01, I10, I11, Ic1, Ic2);

#pragma unroll
    for (int off = 1; off < 32; off <<= 1) {
        float E00 = __shfl_up_sync(~0u, I00, off);
        float E01 = __shfl_up_sync(~0u, I01, off);
        float E10 = __shfl_up_sync(~0u, I10, off);
        float E11 = __shfl_up_sync(~0u, I11, off);
        float Ec1 = __shfl_up_sync(~0u, Ic1, off);
        float Ec2 = __shfl_up_sync(~0u, Ic2, off);
        if (lane >= off) {
            float N00, N01, N10, N11, Nc1, Nc2;
            COMPOSE(E00,E01,E10,E11,Ec1,Ec2, I00,I01,I10,I11,Ic1,Ic2,
                    N00,N01,N10,N11,Nc1,Nc2);
            I00 = N00; I01 = N01; I10 = N10; I11 = N11; Ic1 = Nc1; Ic2 = Nc2;
        }
    }
    float X00 = __shfl_up_sync(~0u, I00, 1);
    float X01 = __shfl_up_sync(~0u, I01, 1);
    float X10 = __shfl_up_sync(~0u, I10, 1);
    float X11 = __shfl_up_sync(~0u, I11, 1);
    float Xc1 = __shfl_up_sync(~0u, Ic1, 1);
    float Xc2 = __shfl_up_sync(~0u, Ic2, 1);
    if (lane == 0) { X00 = 1.f; X01 = 0.f; X10 = 0.f; X11 = 1.f; Xc1 = 0.f; Xc2 = 0.f; }
    if (lane == 31) {
        wagg[wid][0] = I00; wagg[wid][1] = I01; wagg[wid][2] = I10;
        wagg[wid][3] = I11; wagg[wid][4] = Ic1; wagg[wid][5] = Ic2;
    }
    __syncthreads();

    if (wid == 0 && lane < 8) {
        float W00 = wagg[lane][0], W01 = wagg[lane][1], W10 = wagg[lane][2];
        float W11 = wagg[lane][3], Wc1 = wagg[lane][4], Wc2 = wagg[lane][5];
#pragma unroll
        for (int off = 1; off < 8; off <<= 1) {
            float E00 = __shfl_up_sync(0xffu, W00, off);
            float E01 = __shfl_up_sync(0xffu, W01, off);
            float E10 = __shfl_up_sync(0xffu, W10, off);
            float E11 = __shfl_up_sync(0xffu, W11, off);
            float Ec1 = __shfl_up_sync(0xffu, Wc1, off);
            float Ec2 = __shfl_up_sync(0xffu, Wc2, off);
            if (lane >= off) {
                float N00, N01, N10, N11, Nc1, Nc2;
                COMPOSE(E00,E01,E10,E11,Ec1,Ec2, W00,W01,W10,W11,Wc1,Wc2,
                        N00,N01,N10,N11,Nc1,Nc2);
                W00 = N00; W01 = N01; W10 = N10; W11 = N11; Wc1 = Nc1; Wc2 = Nc2;
            }
        }
        float P00 = __shfl_up_sync(0xffu, W00, 1);
        float P01 = __shfl_up_sync(0xffu, W01, 1);
        float P10 = __shfl_up_sync(0xffu, W10, 1);
        float P11 = __shfl_up_sync(0xffu, W11, 1);
        float Pc1 = __shfl_up_sync(0xffu, Wc1, 1);
        float Pc2 = __shfl_up_sync(0xffu, Wc2, 1);
        if (lane == 0) { P00 = 1.f; P01 = 0.f; P10 = 0.f; P11 = 1.f; Pc1 = 0.f; Pc2 = 0.f; }
        sWex[lane][0] = P00; sWex[lane][1] = P01; sWex[lane][2] = P10;
        sWex[lane][3] = P11; sWex[lane][4] = Pc1; sWex[lane][5] = Pc2;
        if (lane == 7) {
            g_chunkM[blk] = make_float4(W00, W01, W10, W11);
            g_chunkC[blk] = make_float2(Wc1, Wc2);
        }
    }
    __syncthreads();

    float E00 = sWex[wid][0], E01 = sWex[wid][1], E10 = sWex[wid][2];
    float E11 = sWex[wid][3], Ec1 = sWex[wid][4], Ec2 = sWex[wid][5];
    float P00, P01, P10, P11, Pc1, Pc2;
    COMPOSE(E00,E01,E10,E11,Ec1,Ec2, X00,X01,X10,X11,Xc1,Xc2,
            P00,P01,P10,P11,Pc1,Pc2);
    int gidx = blk * BTH + tid;
    g_pfxM[gidx] = make_float4(P00, P01, P10, P11);
    g_pfxC[gidx] = make_float2(Pc1, Pc2);
}

// =====================================================================
// K5: incoming chunk states — warp per row, lane per chunk (1 block)
// =====================================================================
__global__ void __launch_bounds__(1024) k_cin() {
    pdl_wait();
    int lane = threadIdx.x & 31;
    int i = threadIdx.x;    // row = tid>>5, chunk = lane; NCHUNK == 32
    float4 M = g_chunkM[i];
    float2 C = g_chunkC[i];
    float T00 = M.x, T01 = M.y, T10 = M.z, T11 = M.w, Tc1 = C.x, Tc2 = C.y;
#pragma unroll
    for (int off = 1; off < 32; off <<= 1) {
        float E00 = __shfl_up_sync(~0u, T00, off);
        float E01 = __shfl_up_sync(~0u, T01, off);
        float E10 = __shfl_up_sync(~0u, T10, off);
        float E11 = __shfl_up_sync(~0u, T11, off);
        float Ec1 = __shfl_up_sync(~0u, Tc1, off);
        float Ec2 = __shfl_up_sync(~0u, Tc2, off);
        if (lane >= off) {
            float N00, N01, N10, N11, Nc1, Nc2;
            COMPOSE(E00,E01,E10,E11,Ec1,Ec2, T00,T01,T10,T11,Tc1,Tc2,
                    N00,N01,N10,N11,Nc1,Nc2);
            T00 = N00; T01 = N01; T10 = N10; T11 = N11; Tc1 = Nc1; Tc2 = Nc2;
        }
    }
    // incoming state (init 0) = c-part of inclusive scan at lane-1
    float p1 = __shfl_up_sync(~0u, Tc1, 1);
    float p2 = __shfl_up_sync(~0u, Tc2, 1);
    if (lane == 0) { p1 = 0.f; p2 = 0.f; }
    g_cin[i] = make_float2(p1, p2);
}

// =====================================================================
// K6: replay — barrier-free, scan-free elementwise
// =====================================================================
__global__ void __launch_bounds__(BTH) k_replay(float* __restrict__ out) {
    int tid = threadIdx.x;
    int blk = blockIdx.x;
    int base = blk * CHUNKN;
    int rowoff = (base >> 16) * SEGCAP;
    int gbase = base + tid * SPT;
    int gidx = blk * BTH + tid;

    // prologue: everything scanA-dependent loads before waiting on k_cin
    float4 PM = g_pfxM[gidx];
    float2 PC = g_pfxC[gidx];
    int ids[SPT];
    unpack_ids(*(const uint4*)&g_segids[gbase], ids);
    bool uni = (ids[0] == ids[SPT - 1]);
    float4 xa = *(const float4*)&g_xc[gbase];
    float4 xb = *(const float4*)&g_xc[gbase + 4];
    float xc[SPT] = { xa.x, xa.y, xa.z, xa.w, xb.x, xb.y, xb.z, xb.w };
    float4 T = g_segA[rowoff + ids[0]];
    float2 Bc = g_segB[rowoff + ids[0]];

    pdl_wait();   // g_cin complete beyond this point

    float2 cin = g_cin[blk];
    float st1 = fmaf(PM.x, cin.x, fmaf(PM.y, cin.y, PC.x));
    float st2 = fmaf(PM.z, cin.x, fmaf(PM.w, cin.y, PC.y));

    float ov[SPT];
#pragma unroll
    for (int i = 0; i < SPT; i++) {
        if (!uni && i) { T = g_segA[rowoff + ids[i]]; Bc = g_segB[rowoff + ids[i]]; }
        ov[i] = fmaf(Bc.x, xc[i], st1);
        float n1 = fmaf(T.z, xc[i], fmaf(T.x, st1, st2));
        float n2 = fmaf(T.w, xc[i], T.y * st1);
        st1 = n1; st2 = n2;
    }
    *(float4*)&out[gbase]     = make_float4(ov[0], ov[1], ov[2], ov[3]);
    *(float4*)&out[gbase + 4] = make_float4(ov[4], ov[5], ov[6], ov[7]);
}

// =====================================================================
template <typename F, typename... Args>
static void launch_pdl(F fn, int grid, int block, Args... args) {
    cudaLaunchConfig_t cfg = {};
    cfg.gridDim = dim3(grid, 1, 1);
    cfg.blockDim = dim3(block, 1, 1);
    cudaLaunchAttribute attr[1];
    attr[0].id = cudaLaunchAttributeProgrammaticStreamSerialization;
    attr[0].val.programmaticStreamSerializationAllowed = 1;
    cfg.attrs = attr;
    cfg.numAttrs = 1;
    cudaLaunchKernelEx(&cfg, fn, args...);
}

extern "C" void kernel_launch(void* const* d_in, const int* in_sizes, int n_in,
                              void* d_out, int out_size) {
    const float* f0     = (const float*)d_in[0];
    const float* x      = (const float*)d_in[1];
    const float* params = (const float*)d_in[2];
    const int*   onsets = (const int*)d_in[3];
    float* out = (float*)d_out;

    k_tile<<<Bn * NT, 256>>>((const int4*)onsets);
    launch_pdl(k_ids,    Bn * NT, 256, (const int4*)onsets, (const float4*)params);
    launch_pdl(k_segc,   Bn,      256);
    launch_pdl(k_scanA,  NBLK,    BTH, x, f0);
    launch_pdl(k_cin,    1,       1024);
    launch_pdl(k_replay, NBLK,    BTH, out);
}